// round 3
// baseline (speedup 1.0000x reference)
#include <cuda_runtime.h>
#include <cstdint>

#define FEAT_DIM     1024
#define MAX_BATCH    65536
#define ROWS_PER_BLK 8
#define MAX_BLOCKS   (MAX_BATCH / ROWS_PER_BLK)

// Scratch (allocation-free per harness rules)
__device__ float g_partials[MAX_BLOCKS];
__device__ int   g_label_is_i64;

// ---------------------------------------------------------------------------
// Probe: distinguish int64 vs int32 label storage.
// int64 little-endian with values in [0,96) => every odd 32-bit word is 0.
// 64 consecutive zero odd-words from genuine int32 labels ~ (1/96)^64 ~ 0.
// ---------------------------------------------------------------------------
__global__ void probe_label_dtype(const unsigned int* __restrict__ lw) {
    if (threadIdx.x == 0) {
        int is64 = 1;
        #pragma unroll 8
        for (int i = 0; i < 64; i++) {
            if (lw[2 * i + 1] != 0u) { is64 = 0; break; }
        }
        g_label_is_i64 = is64;
    }
}

// ---------------------------------------------------------------------------
// Main: one warp per row. 8 x float4 coalesced loads/lane from features (DRAM)
// and from the label's center row (L2-resident, 384 KB total).
// ---------------------------------------------------------------------------
__global__ void __launch_bounds__(256, 8)
center_loss_rows(const float* __restrict__ feat,
                 const float* __restrict__ centers,
                 const unsigned int* __restrict__ label_words) {
    const int warp = threadIdx.x >> 5;
    const int lane = threadIdx.x & 31;
    const int row  = blockIdx.x * ROWS_PER_BLK + warp;

    int label = 0;
    if (lane == 0) {
        label = g_label_is_i64 ? (int)label_words[2 * row]
                               : (int)label_words[row];
    }
    label = __shfl_sync(0xffffffffu, label, 0);

    const float4* fr = (const float4*)(feat    + (size_t)row   * FEAT_DIM);
    const float4* cr = (const float4*)(centers + (size_t)label * FEAT_DIM);

    float acc = 0.0f;
    #pragma unroll
    for (int i = 0; i < FEAT_DIM / (4 * 32); i++) {   // 8 iterations
        float4 a = fr[lane + 32 * i];
        float4 b = cr[lane + 32 * i];
        float dx = a.x - b.x, dy = a.y - b.y, dz = a.z - b.z, dw = a.w - b.w;
        acc = fmaf(dx, dx, acc);
        acc = fmaf(dy, dy, acc);
        acc = fmaf(dz, dz, acc);
        acc = fmaf(dw, dw, acc);
    }

    // warp reduce
    #pragma unroll
    for (int o = 16; o > 0; o >>= 1)
        acc += __shfl_xor_sync(0xffffffffu, acc, o);

    __shared__ float s[ROWS_PER_BLK];
    if (lane == 0) {
        // clamp matches reference clip(d, 1e-12, 1e12) on the label column
        float d = fminf(fmaxf(acc, 1e-12f), 1e12f);
        s[warp] = d;
    }
    __syncthreads();

    if (threadIdx.x == 0) {
        float t = 0.0f;
        #pragma unroll
        for (int i = 0; i < ROWS_PER_BLK; i++) t += s[i];
        g_partials[blockIdx.x] = t;
    }
}

// ---------------------------------------------------------------------------
// Final reduce: 1 block, double accumulation (8192 adds, negligible cost),
// writes scalar loss = mean + (C-1)*1e-12 (the clipped zero columns).
// ---------------------------------------------------------------------------
__global__ void center_loss_reduce(float* __restrict__ out,
                                   int n_partials, int batch, int num_classes) {
    double acc = 0.0;
    for (int i = threadIdx.x; i < n_partials; i += blockDim.x)
        acc += (double)g_partials[i];

    __shared__ double s[256];
    s[threadIdx.x] = acc;
    __syncthreads();
    for (int stride = 128; stride > 0; stride >>= 1) {
        if (threadIdx.x < stride) s[threadIdx.x] += s[threadIdx.x + stride];
        __syncthreads();
    }
    if (threadIdx.x == 0) {
        double loss = s[0] / (double)batch
                    + (double)(num_classes - 1) * 1e-12;
        out[0] = (float)loss;
    }
}

// ---------------------------------------------------------------------------
extern "C" void kernel_launch(void* const* d_in, const int* in_sizes, int n_in,
                              void* d_out, int out_size) {
    const float*        feat    = (const float*)d_in[0];
    const float*        centers = (const float*)d_in[1];
    const unsigned int* labels  = (const unsigned int*)d_in[2];

    const int batch       = in_sizes[0] / FEAT_DIM;   // 65536
    const int num_classes = in_sizes[1] / FEAT_DIM;   // 96
    const int nblocks     = batch / ROWS_PER_BLK;     // 8192

    probe_label_dtype<<<1, 32>>>(labels);
    center_loss_rows<<<nblocks, 256>>>(feat, centers, labels);
    center_loss_reduce<<<1, 256>>>((float*)d_out, nblocks, batch, num_classes);
}